// round 11
// baseline (speedup 1.0000x reference)
#include <cuda_runtime.h>
#include <cuda_bf16.h>

#define TICKS   1000
#define TPAD    1024        // TICKS rounded up to 32 — sim chunks read the pad
#define NTAPS   49
#define KW      7
#define OUT_CH  128
#define MAXD    14          // 6 + min(stride,8)
#define MAXC    (MAXD*MAXD) // 196

// ---- scratch (no allocations allowed) ----
// Transposed layout: hist[cls][t] -> warp-coalesced loads over t in sim Phase B.
__device__ __align__(16) float d_hist[MAXC * TICKS];

__device__ __forceinline__ int imin(int a, int b) { return a < b ? a : b; }

// ------------------------------------------------------------------
// 1) event scatter into hist[cls][t].
//    stride==2 fast path: the 4 hot classes (x>=6 && y>=6, 91% of events)
//    aggregate in shared memory (ATOMS), flushed once per CTA. Cold events
//    + generic strides go straight to L2 via RED.F32 (no return -> no
//    scoreboard stalls). spike_values are 1.0f so per-slot sums are exact
//    integers: atomic ordering cannot perturb results.
// ------------------------------------------------------------------
__global__ void __launch_bounds__(1024) scatter_kernel(
    const int* __restrict__ tk, const int* __restrict__ xs,
    const int* __restrict__ ys, const float* __restrict__ vs,
    const int* __restrict__ sp, int n)
{
    __shared__ float sh[4 * 1024];             // [hot][t], t padded to 1024
    const int stride = *sp;
    const int D  = 6 + imin(stride, 8);
    const bool s2 = (stride == 2);

    if (s2) {
        for (int i = threadIdx.x; i < 4 * 1024; i += blockDim.x) sh[i] = 0.f;
        __syncthreads();
    }

    const int tid = blockIdx.x * blockDim.x + threadIdx.x;
    const int nth = gridDim.x * blockDim.x;

    auto proc = [&](int t, int x, int y, float v) {
        if (s2) {                                // warp-uniform branch
            if (x >= 6 && y >= 6) {              // hot: smem ATOMS
                int h = ((y & 1) << 1) | (x & 1);
                atomicAdd(&sh[h * 1024 + t], v);
            } else {                             // cold (~9%): global RED
                int cx = (x < 6) ? x : 6 + (x & 1);
                int cy = (y < 6) ? y : 6 + (y & 1);
                atomicAdd(&d_hist[(cy * 8 + cx) * TICKS + t], v);
            }
        } else {
            int cx = (x < 6) ? x : 6 + imin(x % stride, 7);
            int cy = (y < 6) ? y : 6 + imin(y % stride, 7);
            atomicAdd(&d_hist[(cy * D + cx) * TICKS + t], v);
        }
    };

    const int n4 = n >> 2;
    const int4*   t4 = reinterpret_cast<const int4*>(tk);
    const int4*   x4 = reinterpret_cast<const int4*>(xs);
    const int4*   y4 = reinterpret_cast<const int4*>(ys);
    const float4* v4 = reinterpret_cast<const float4*>(vs);

    for (int i = tid; i < n4; i += nth) {
        int4   a = t4[i];
        int4   b = x4[i];
        int4   c = y4[i];
        float4 w = v4[i];
        proc(a.x, b.x, c.x, w.x);
        proc(a.y, b.y, c.y, w.y);
        proc(a.z, b.z, c.z, w.z);
        proc(a.w, b.w, c.w, w.w);
    }
    for (int i = (n4 << 2) + tid; i < n; i += nth)
        proc(tk[i], xs[i], ys[i], vs[i]);

    if (s2) {
        __syncthreads();
        // flush hot classes: stride=2 -> D=8, cls = (6+ry)*8 + (6+rx) = 54+8ry+rx
        for (int i = threadIdx.x; i < 4 * TICKS; i += blockDim.x) {
            int h = i / TICKS, t = i - h * TICKS;
            float val = sh[h * 1024 + t];
            if (val != 0.f) {
                int cls = 54 + 8 * (h >> 1) + (h & 1);
                atomicAdd(&d_hist[cls * TICKS + t], val);
            }
        }
    }
}

// ------------------------------------------------------------------
// 2) fused drive + Izhikevich sim. One 1024-thread block per channel.
//    Phase A: class weights (shared).
//    Phase B: one tick per thread — warp lanes read consecutive t of the
//             same hist row (coalesced LDG.32). Single sequential
//             accumulator over cls (unchanged order -> bit-identical g).
//    Phase C: warp 0, serial recurrence with threshold speculation.
//             Drive values are FORCE-hoisted: 32 ld.volatile.shared.f32
//             issued at chunk start (nvvm cannot sink volatiles; R10
//             showed ptxas sinking plain LDS onto the S->I->v chain,
//             costing ~21cyc/tick). Arithmetic byte-identical to R9/R10.
// ------------------------------------------------------------------
__global__ void __launch_bounds__(1024) sim_kernel(
    const float* __restrict__ w, const int* __restrict__ sp,
    float* __restrict__ out)
{
    __shared__ float wc[MAXC];
    __shared__ float sg[TPAD + 4];

    const int c   = blockIdx.x;
    const int tid = threadIdx.x;
    const int stride = *sp;
    const int D = 6 + imin(stride, 8);
    const int C = D * D;

    // ---- Phase A: class weights for this channel ----
    if (tid < C) {
        const int cls = tid;
        const int cy = cls / D, cx = cls % D;
        int sx, lx, sy, ly;
        if (cx < 6) { sx = cx % stride; lx = cx; } else { sx = cx - 6; lx = 6; }
        if (cy < 6) { sy = cy % stride; ly = cy; } else { sy = cy - 6; ly = 6; }
        float acc = 0.f;
        for (int ky = sy; ky <= ly; ky += stride)
            for (int kx = sx; kx <= lx; kx += stride)
                acc += w[c * NTAPS + ky * KW + kx];
        wc[cls] = acc;
    }
    // zero sg (covers sg[0] and the pad)
    for (int i = tid; i < TPAD + 4; i += blockDim.x) sg[i] = 0.f;
    __syncthreads();

    // ---- Phase B: sg[t] = dot(wc, hist[:, t-1]) for t in [1, TICKS] ----
    if (tid >= 1 && tid <= TICKS) {
        const int tm1 = tid - 1;                  // source tick
        const float* __restrict__ hp = d_hist + tm1;
        float acc = 0.f;
        #pragma unroll 16
        for (int cls = 0; cls < C; ++cls)
            acc = fmaf(wc[cls], __ldg(&hp[cls * TICKS]), acc);
        sg[tid] = acc;                            // 1-tick synaptic delay
    }
    __syncthreads();

    // ---- Phase C: serial sim, warp 0 only ----
    if (tid >= 32) return;
    const int lane = tid;

    float* __restrict__ ospk = out + c * TICKS;
    float* __restrict__ ovtr = out + OUT_CH * TICKS + c * TICKS;

    const float decay = 0.9f;                        // 1 - dt/tau_fall
    const float h     = (float)(0.001 / 150.0);      // dt / C
    const float Kp = 1.2f, VR = -75.f, VT = -45.f;
    const float AP = 0.01f, BP = 5.f, VP = 50.f;
    const float DP = 130.f, VRS = -56.f, IIN = 350.f, DT = 0.001f;
    // constant-folded spike-path product: Kp*(VRS-VR)*(VRS-VT), same RN
    // rounding the runtime FADD/FMULs produce (19 and -11 are exact).
    const float QC = 1.2f * (VRS - VR) * (VRS - VT);

    const unsigned sg_smem =
        (unsigned)__cvta_generic_to_shared(sg);      // shared-space base

    // carry: vpre = v BEFORE reset of previous tick; spprev = its spike bit.
    float vpre = VR, u = 0.f, S = 0.f;
    bool  spprev = false;

    for (int t0 = 0; t0 < TICKS; t0 += 32) {
        // force-issue all 32 drive loads NOW (volatile: cannot be sunk)
        float gv[32];
        const unsigned base = sg_smem + (unsigned)t0 * 4u;
        #pragma unroll
        for (int j = 0; j < 32; ++j)
            asm volatile("ld.volatile.shared.f32 %0, [%1];"
                         : "=f"(gv[j]) : "r"(base + 4u * j));

        float keepv = 0.f, keeps = 0.f;
        #pragma unroll
        for (int i = 0; i < 32; ++i) {
            float gt = gv[i];
            S = S * decay + gt;                      // summed synapse state
            float I = IIN + S;                       // I_bias = 0
            // both candidates, computed before spprev's select:
            float vn  = vpre + (Kp * (vpre - VR) * (vpre - VT) - u + I) * h;
            float vsp = VRS  + (QC - u + I) * h;     // chains via u,I only
            float vnew = spprev ? vsp : vn;          // FSEL (pred-as-data)
            // u update uses pre-reset v (reference order)
            float unew = u + AP * (BP * (vnew - VR) - u) * DT;
            bool sp_ = vnew >= VP;
            float spf   = sp_ ? 1.f : 0.f;
            float vpost = sp_ ? VRS : vnew;          // output value only
            u = sp_ ? unew + DP : unew;
            vpre = vnew; spprev = sp_;
            keepv = (lane == i) ? vpost : keepv;     // register-keep, off chain
            keeps = (lane == i) ? spf   : keeps;
        }
        int t = t0 + lane;
        if (t < TICKS) {                             // guard: 1000 % 32 != 0
            ospk[t] = keeps;                         // coalesced per chunk
            ovtr[t] = keepv;
        }
    }
}

// ------------------------------------------------------------------
extern "C" void kernel_launch(void* const* d_in, const int* in_sizes, int n_in,
                              void* d_out, int out_size)
{
    const int*   tk = (const int*)  d_in[0];   // spike_ticks
    const int*   xs = (const int*)  d_in[1];   // spike_x
    const int*   ys = (const int*)  d_in[2];   // spike_y
    const float* vs = (const float*)d_in[3];   // spike_values
    const float* w  = (const float*)d_in[4];   // weights [128,49]
    const int*   sp = (const int*)  d_in[5];   // stride
    const int    n  = in_sizes[0];

    void* hist_ptr = nullptr;
    cudaGetSymbolAddress(&hist_ptr, d_hist);
    cudaMemsetAsync(hist_ptr, 0, sizeof(float) * MAXC * TICKS);   // memset node

    scatter_kernel<<<148, 1024>>>(tk, xs, ys, vs, sp, n);
    sim_kernel<<<OUT_CH, 1024>>>(w, sp, (float*)d_out);
}